// round 15
// baseline (speedup 1.0000x reference)
#include <cuda_runtime.h>
#include <cstdint>

// Fixed shapes
#define B_TOTAL   65536
#define P_DIM     41
#define NROWS     (B_TOTAL * P_DIM)        // 2686976 rows of 4 lanes (L=4)
#define THREADS   256
#define WARPS_PB  8
#define USEFUL    28                        // useful rows per warp-chunk (lanes 2..29)
#define ITER      6
#define SPAN      (USEFUL * ITER)           // 168 rows per warp
#define ROWS_PB   (SPAN * WARPS_PB)         // 1344 rows per block
#define NBLOCKS   ((NROWS + ROWS_PB - 1) / ROWS_PB)   // 2000

#define DEPTH     3                          // cp.async ring stages
#define PREF      2                          // prefetch distance
#define STAGE_B   1536                       // bytes per warp-stage: 3 arrays * 32 lanes * 16B

__device__ float        g_partials[NBLOCKS];
__device__ unsigned int g_count = 0;        // ticket; returns to 0 every launch

__device__ __forceinline__ uint32_t smem_u32(const void* p) {
    uint32_t a;
    asm("{ .reg .u64 t; cvta.to.shared.u64 t, %1; cvt.u32.u64 %0, t; }" : "=r"(a) : "l"(p));
    return a;
}
__device__ __forceinline__ void cp16(uint32_t dst, const void* src) {
    asm volatile("cp.async.ca.shared.global [%0], [%1], 16;" :: "r"(dst), "l"(src) : "memory");
}
#define CP_COMMIT() asm volatile("cp.async.commit_group;" ::: "memory")
#define CP_WAIT2()  asm volatile("cp.async.wait_group 2;" ::: "memory")

__global__ __launch_bounds__(THREADS, 4)
void lace_kernel(const float* __restrict__ logits,
                 const int* __restrict__ targets,
                 float* __restrict__ out)
{
    __shared__ __align__(16) char ring[WARPS_PB][DEPTH][STAGE_B];   // 36864 B
    __shared__ float warpsums[WARPS_PB];
    __shared__ float redsums[WARPS_PB];
    __shared__ bool  isLast;

    const int tid   = threadIdx.x;
    const int lane  = tid & 31;
    const int wid   = tid >> 5;
    const int gwarp = blockIdx.x * WARPS_PB + wid;

    const float4* __restrict__ gL = (const float4*)logits;   // 82 float4 per batch
    const int4*   __restrict__ gT = (const int4*)targets;    // 1 int4 per row

    const bool laneOK = (lane >= 2 && lane <= 29);
    const int  rbase  = gwarp * SPAN + lane - 2;

    // thread-private smem slot base (stage 0); stages advance by STAGE_B
    const uint32_t slot0 = smem_u32(&ring[wid][0][0]) + (uint32_t)lane * 16u;

    // issue one stage: 3 x 16B cp.async into this thread's slots
    auto issue_stage = [&](int s, int slot) {
        const int rl = rbase + s * USEFUL;
        const int r  = min(max(rl, 0), NROWS - 1);
        const int b  = (int)((unsigned)r / 41u);
        const int idx0 = r + b * 41;                         // = b*82 + p
        const uint32_t base = slot0 + (uint32_t)slot * STAGE_B;
        cp16(base,         gL + idx0);                       // v0
        cp16(base + 512u,  gL + idx0 + 41);                  // v1
        cp16(base + 1024u, gT + r);                          // tg
    };

    // prologue: stages 0..PREF-1
    issue_stage(0, 0); CP_COMMIT();
    issue_stage(1, 1); CP_COMMIT();

    float acc     = 0.0f;
    int   connAcc = 0;

    #pragma unroll
    for (int c = 0; c < ITER; ++c) {
        // issue stage c+PREF (or empty commit in tail to keep group numbering)
        if (c + PREF < ITER) issue_stage(c + PREF, (c + PREF) % DEPTH);
        CP_COMMIT();
        CP_WAIT2();                                          // stage c complete

        // ---- consume stage c from smem ----
        const uint32_t base = slot0 + (uint32_t)(c % DEPTH) * STAGE_B;
        float4 v0, v1; int4 tg;
        asm volatile("ld.shared.v4.f32 {%0,%1,%2,%3}, [%4];"
                     : "=f"(v0.x), "=f"(v0.y), "=f"(v0.z), "=f"(v0.w) : "r"(base));
        asm volatile("ld.shared.v4.f32 {%0,%1,%2,%3}, [%4];"
                     : "=f"(v1.x), "=f"(v1.y), "=f"(v1.z), "=f"(v1.w) : "r"(base + 512u));
        asm volatile("ld.shared.v4.b32 {%0,%1,%2,%3}, [%4];"
                     : "=r"(tg.x), "=r"(tg.y), "=r"(tg.z), "=r"(tg.w) : "r"(base + 1024u));

        const int rl = rbase + c * USEFUL;
        const int r  = min(max(rl, 0), NROWS - 1);
        const int p  = r - (int)((unsigned)r / 41u) * 41;
        const bool valid = laneOK && (rl < NROWS);

        const float ne0 = v0.x - v1.x, ne1 = v0.y - v1.y;
        const float ne2 = v0.z - v1.z, ne3 = v0.w - v1.w;

        // pk: per-l byte, bit6 = target, bit7 = pred (l1>l0 <=> ne<0)
        unsigned pa = __byte_perm((unsigned)tg.x, (unsigned)tg.y, 0x0040);
        unsigned pb = __byte_perm((unsigned)tg.z, (unsigned)tg.w, 0x0040);
        unsigned sT = __byte_perm(pa, pb, 0x5410);
        unsigned qa = __byte_perm(__float_as_uint(ne0), __float_as_uint(ne1), 0x0073);
        unsigned qb = __byte_perm(__float_as_uint(ne2), __float_as_uint(ne3), 0x0073);
        unsigned sP = __byte_perm(qa, qb, 0x5410);
        unsigned pk = (sT << 6) | (sP & 0x80808080u);

        // batch-boundary-clamped shuffle sources (clamp-to-self zeroes the xor)
        int sm1 = (p == 0)          ? lane : lane - 1;
        int sm2 = (p <= 1)          ? lane : lane - 2;
        int sp1 = (p == P_DIM - 1)  ? lane : lane + 1;
        int sp2 = (p >= P_DIM - 2)  ? lane : lane + 2;

        unsigned pkm1 = __shfl_sync(0xffffffffu, pk, sm1);
        unsigned pkm2 = __shfl_sync(0xffffffffu, pk, sm2);
        unsigned pkp1 = __shfl_sync(0xffffffffu, pk, sp1);
        unsigned pkp2 = __shfl_sync(0xffffffffu, pk, sp2);

        unsigned xm1 = pk ^ pkm1;
        unsigned xm2 = pk ^ pkm2;
        unsigned xp1 = pk ^ pkp1;
        unsigned xp2 = pk ^ pkp2;

        // connectivity: pred-xor vs p-1 (bit7/byte), masked, integer accumulate
        unsigned maskC = valid ? 0x80808080u : 0u;
        connAcc += __popc(xm1 & maskC);

        // weight bytes: value = 2w-2 in [0,6] per byte
        unsigned w1 = ((xm1 >> 6) & 0x01010101u) + ((xp1 >> 6) & 0x01010101u);
        unsigned w2 = ((xm2 >> 6) & 0x01010101u) + ((xp2 >> 6) & 0x01010101u);
        unsigned wb = w1 + w1 + w2;

        // mis = t ^ pred at bit7 of each byte
        unsigned misW = (pk << 1) ^ pk;

        const float vf = valid ? 1.0f : 0.0f;
        const float hv = valid ? 0.5f : 0.0f;

        const float nes[4] = {ne0, ne1, ne2, ne3};
        #pragma unroll
        for (int l = 0; l < 4; ++l) {
            float ae = fabsf(nes[l]);
            // softplus(d) = mis*|ne| + log(1 + exp(-|ne|))
            float ex  = __expf(-ae);
            float sp  = __logf(1.0f + ex);
            float z   = ((misW >> (8 * l + 7)) & 1u) ? ae : 0.0f;
            float loss = z + sp;
            float fb  = (float)((wb >> (8 * l)) & 0xFFu);      // 2w-2
            float wf  = fmaf(fb, hv, vf);                      // = valid * w
            acc = fmaf(loss, wf, acc);
        }
    }

    acc = fmaf(0.001f, (float)connAcc, acc);

    // warp reduce -> block partial
    #pragma unroll
    for (int o = 16; o > 0; o >>= 1)
        acc += __shfl_down_sync(0xffffffffu, acc, o);
    if (lane == 0) warpsums[wid] = acc;
    __syncthreads();

    if (tid == 0) {
        float bs = 0.0f;
        #pragma unroll
        for (int k = 0; k < WARPS_PB; ++k) bs += warpsums[k];
        g_partials[blockIdx.x] = bs;
        __threadfence();
        unsigned int old = atomicAdd(&g_count, 1u);
        isLast = (old == NBLOCKS - 1);
    }
    __syncthreads();

    // last block: deterministic fixed-order reduction of all partials
    if (isLast) {
        float s = 0.0f;
        #pragma unroll
        for (int k = 0; k < (NBLOCKS + THREADS - 1) / THREADS; ++k) {
            int idx = tid + k * THREADS;
            if (idx < NBLOCKS) s += g_partials[idx];
        }
        #pragma unroll
        for (int o = 16; o > 0; o >>= 1)
            s += __shfl_down_sync(0xffffffffu, s, o);
        if (lane == 0) redsums[wid] = s;
        __syncthreads();
        if (tid == 0) {
            float t = 0.0f;
            #pragma unroll
            for (int k = 0; k < WARPS_PB; ++k) t += redsums[k];
            out[0] = t * (1.0f / ((float)B_TOTAL * (float)P_DIM * 4.0f));
            g_count = 0;   // reset for next graph replay
        }
    }
}

extern "C" void kernel_launch(void* const* d_in, const int* in_sizes, int n_in,
                              void* d_out, int out_size)
{
    const float* logits  = (const float*)d_in[0];
    const int*   targets = (const int*)d_in[1];
    float*       out     = (float*)d_out;

    lace_kernel<<<NBLOCKS, THREADS>>>(logits, targets, out);
}

// round 16
// speedup vs baseline: 1.1737x; 1.1737x over previous
#include <cuda_runtime.h>
#include <cstdint>

// Fixed shapes
#define B_TOTAL   65536
#define P_DIM     41
#define NROWS     (B_TOTAL * P_DIM)        // 2686976 rows of 4 lanes (L=4)
#define THREADS   256
#define WARPS_PB  8
#define USEFUL    28                        // useful rows per warp-chunk (lanes 2..29)
#define ITER      6
#define SPAN      (USEFUL * ITER)           // 168 rows per warp
#define ROWS_PB   (SPAN * WARPS_PB)         // 1344 rows per block
#define NBLOCKS   ((NROWS + ROWS_PB - 1) / ROWS_PB)   // 2000

__device__ float        g_partials[NBLOCKS];
__device__ unsigned int g_count = 0;        // ticket; returns to 0 every launch

struct Row {
    float4 v0, v1;
    int4   tg;
    int    rl;
};

__device__ __forceinline__ Row load_row(const float4* __restrict__ gL,
                                        const int4* __restrict__ gT, int rl)
{
    Row x;
    x.rl = rl;
    const int r = min(max(rl, 0), NROWS - 1);
    const int b = (int)((unsigned)r / 41u);
    const int idx0 = r + b * 41;             // = b*82 + p
    // L1-bypass streaming loads (cached in L2 only; halo reuse is L2-served)
    x.v0 = __ldcg(gL + idx0);                // class 0
    x.v1 = __ldcg(gL + idx0 + 41);           // class 1
    x.tg = __ldcg(gT + r);
    return x;
}

__global__ __launch_bounds__(THREADS, 4)
void lace_kernel(const float* __restrict__ logits,
                 const int* __restrict__ targets,
                 float* __restrict__ out)
{
    __shared__ float warpsums[WARPS_PB];
    __shared__ float redsums[WARPS_PB];
    __shared__ bool  isLast;

    const int tid   = threadIdx.x;
    const int lane  = tid & 31;
    const int wid   = tid >> 5;
    const int gwarp = blockIdx.x * WARPS_PB + wid;

    const float4* __restrict__ gL = (const float4*)logits;   // 82 float4 per batch
    const int4*   __restrict__ gT = (const int4*)targets;    // 1 int4 per row

    const bool laneOK = (lane >= 2 && lane <= 29);
    const int  rbase  = gwarp * SPAN + lane - 2;

    float acc     = 0.0f;
    int   connAcc = 0;

    Row cur = load_row(gL, gT, rbase);

    #pragma unroll
    for (int c = 0; c < ITER; ++c) {
        // ---- prefetch next iteration BEFORE computing current ----
        Row nxt = (c + 1 < ITER) ? load_row(gL, gT, rbase + (c + 1) * USEFUL) : cur;

        // ---- compute on cur ----
        const int rl = cur.rl;
        const int r  = min(max(rl, 0), NROWS - 1);
        const int p  = r - (int)((unsigned)r / 41u) * 41;
        const bool valid = laneOK && (rl < NROWS);

        const float ne0 = cur.v0.x - cur.v1.x, ne1 = cur.v0.y - cur.v1.y;
        const float ne2 = cur.v0.z - cur.v1.z, ne3 = cur.v0.w - cur.v1.w;

        // pk: per-l byte, bit6 = target, bit7 = pred (l1>l0 <=> ne<0)
        unsigned pa = __byte_perm((unsigned)cur.tg.x, (unsigned)cur.tg.y, 0x0040);
        unsigned pb = __byte_perm((unsigned)cur.tg.z, (unsigned)cur.tg.w, 0x0040);
        unsigned sT = __byte_perm(pa, pb, 0x5410);
        unsigned qa = __byte_perm(__float_as_uint(ne0), __float_as_uint(ne1), 0x0073);
        unsigned qb = __byte_perm(__float_as_uint(ne2), __float_as_uint(ne3), 0x0073);
        unsigned sP = __byte_perm(qa, qb, 0x5410);
        unsigned pk = (sT << 6) | (sP & 0x80808080u);

        // batch-boundary-clamped shuffle sources (clamp-to-self zeroes the xor)
        int sm1 = (p == 0)          ? lane : lane - 1;
        int sm2 = (p <= 1)          ? lane : lane - 2;
        int sp1 = (p == P_DIM - 1)  ? lane : lane + 1;
        int sp2 = (p >= P_DIM - 2)  ? lane : lane + 2;

        unsigned pkm1 = __shfl_sync(0xffffffffu, pk, sm1);
        unsigned pkm2 = __shfl_sync(0xffffffffu, pk, sm2);
        unsigned pkp1 = __shfl_sync(0xffffffffu, pk, sp1);
        unsigned pkp2 = __shfl_sync(0xffffffffu, pk, sp2);

        unsigned xm1 = pk ^ pkm1;
        unsigned xm2 = pk ^ pkm2;
        unsigned xp1 = pk ^ pkp1;
        unsigned xp2 = pk ^ pkp2;

        // connectivity: pred-xor vs p-1 (bit7/byte), masked, integer accumulate
        unsigned maskC = valid ? 0x80808080u : 0u;
        connAcc += __popc(xm1 & maskC);

        // weight bytes: value = 2w-2 in [0,6] per byte
        unsigned w1 = ((xm1 >> 6) & 0x01010101u) + ((xp1 >> 6) & 0x01010101u);
        unsigned w2 = ((xm2 >> 6) & 0x01010101u) + ((xp2 >> 6) & 0x01010101u);
        unsigned wb = w1 + w1 + w2;

        // mis = t ^ pred at bit7 of each byte
        unsigned misW = (pk << 1) ^ pk;

        const float vf = valid ? 1.0f : 0.0f;
        const float hv = valid ? 0.5f : 0.0f;

        const float nes[4] = {ne0, ne1, ne2, ne3};
        #pragma unroll
        for (int l = 0; l < 4; ++l) {
            float ae = fabsf(nes[l]);
            // softplus(d) = mis*|ne| + log(1 + exp(-|ne|))
            float ex  = __expf(-ae);
            float sp  = __logf(1.0f + ex);
            float z   = ((misW >> (8 * l + 7)) & 1u) ? ae : 0.0f;
            float loss = z + sp;
            float fb  = (float)((wb >> (8 * l)) & 0xFFu);      // 2w-2
            float wf  = fmaf(fb, hv, vf);                      // = valid * w
            acc = fmaf(loss, wf, acc);
        }

        cur = nxt;
    }

    acc = fmaf(0.001f, (float)connAcc, acc);

    // warp reduce -> block partial
    #pragma unroll
    for (int o = 16; o > 0; o >>= 1)
        acc += __shfl_down_sync(0xffffffffu, acc, o);
    if (lane == 0) warpsums[wid] = acc;
    __syncthreads();

    if (tid == 0) {
        float bs = 0.0f;
        #pragma unroll
        for (int k = 0; k < WARPS_PB; ++k) bs += warpsums[k];
        g_partials[blockIdx.x] = bs;
        __threadfence();
        unsigned int old = atomicAdd(&g_count, 1u);
        isLast = (old == NBLOCKS - 1);
    }
    __syncthreads();

    // last block: deterministic fixed-order reduction of all partials
    if (isLast) {
        float s = 0.0f;
        #pragma unroll
        for (int k = 0; k < (NBLOCKS + THREADS - 1) / THREADS; ++k) {
            int idx = tid + k * THREADS;
            if (idx < NBLOCKS) s += g_partials[idx];
        }
        #pragma unroll
        for (int o = 16; o > 0; o >>= 1)
            s += __shfl_down_sync(0xffffffffu, s, o);
        if (lane == 0) redsums[wid] = s;
        __syncthreads();
        if (tid == 0) {
            float t = 0.0f;
            #pragma unroll
            for (int k = 0; k < WARPS_PB; ++k) t += redsums[k];
            out[0] = t * (1.0f / ((float)B_TOTAL * (float)P_DIM * 4.0f));
            g_count = 0;   // reset for next graph replay
        }
    }
}

extern "C" void kernel_launch(void* const* d_in, const int* in_sizes, int n_in,
                              void* d_out, int out_size)
{
    const float* logits  = (const float*)d_in[0];
    const int*   targets = (const int*)d_in[1];
    float*       out     = (float*)d_out;

    lace_kernel<<<NBLOCKS, THREADS>>>(logits, targets, out);
}